// round 1
// baseline (speedup 1.0000x reference)
#include <cuda_runtime.h>
#include <math.h>

#define NB 8
#define NA 49104
#define NC 80
#define NBC (NB*NC)
#define KPRE 256
#define CAP 12288
#define MAXPC 100
#define MAXTOT 100
#define CANDCAP (NC*MAXPC)
#define THRL -2.9444389791664403f

// ---------------- scratch (static device globals; no runtime allocation) ----
static __device__ int g_cnt[NBC];
static __device__ unsigned long long g_bucket[(size_t)NBC*CAP];
static __device__ int g_ccnt[NB];
static __device__ unsigned long long g_ckey[NB*CANDCAP];
static __device__ float4 g_cbox[NB*CANDCAP];

__device__ __forceinline__ unsigned fkey(float f){
    unsigned u = __float_as_uint(f);
    return (u & 0x80000000u) ? ~u : (u | 0x80000000u);
}
__device__ __forceinline__ float finv(unsigned o){
    unsigned u = (o & 0x80000000u) ? (o & 0x7FFFFFFFu) : ~o;
    return __uint_as_float(u);
}

// ---------------- kernel 0: zero counters --------------------------------
__global__ void k_zero(){
    int t = blockIdx.x*blockDim.x + threadIdx.x;
    if (t < NBC) g_cnt[t] = 0;
    if (t < NB)  g_ccnt[t] = 0;
}

// ---------------- kernel 1: threshold filter + bucket scatter -------------
__global__ void __launch_bounds__(256) k_filter(const float4* __restrict__ ycls){
    const long long tot4 = (long long)NB*NA*NC/4;
    long long stride = (long long)gridDim.x*blockDim.x;
    for (long long g = blockIdx.x*(long long)blockDim.x + threadIdx.x; g < tot4; g += stride){
        float4 v = ycls[g];
        if (v.x > THRL || v.y > THRL || v.z > THRL || v.w > THRL){
            long long i0 = g*4;
            long long t  = i0 / NC;
            int c0 = (int)(i0 - t*NC);       // multiple of 4, so c0..c0+3 stay in one anchor
            int a  = (int)(t % NA);
            int b  = (int)(t / NA);
            unsigned inva = 0xFFFFFFFFu - (unsigned)a;
            float vv[4] = {v.x, v.y, v.z, v.w};
            #pragma unroll
            for (int k = 0; k < 4; k++){
                if (vv[k] > THRL){
                    int bc = b*NC + c0 + k;
                    int pos = atomicAdd(&g_cnt[bc], 1);
                    if (pos < CAP)
                        g_bucket[(size_t)bc*CAP + pos] =
                            ((unsigned long long)fkey(vv[k]) << 32) | inva;
                }
            }
        }
    }
}

// ---------------- kernel 2: per-(b,c) top-256 + NMS@0.5 -------------------
__global__ void __launch_bounds__(256) k_class(const float4* __restrict__ ybbox,
                                               const float4* __restrict__ anchors){
    int bc = blockIdx.x, b = bc/NC, c = bc - b*NC, tid = threadIdx.x;
    int n = g_cnt[bc]; n = n > CAP ? CAP : n;
    if (n == 0) return;
    const unsigned long long* __restrict__ bucket = &g_bucket[(size_t)bc*CAP];

    __shared__ unsigned hist[256];
    __shared__ unsigned sh_prefix;
    __shared__ int sh_need, sn;
    __shared__ unsigned long long skey[512];

    if (n <= KPRE){
        for (int i = tid; i < 512; i += 256) skey[i] = (i < n) ? bucket[i] : 0ull;
    } else {
        // 4-level radix select: find exact 32-bit cutoff key for rank 256
        unsigned prefix = 0; int need = KPRE;
        for (int shift = 24; shift >= 0; shift -= 8){
            hist[tid] = 0;
            __syncthreads();
            unsigned hm = (shift == 24) ? 0u : (0xFFFFFFFFu << (shift+8));
            for (int i = tid; i < n; i += 256){
                unsigned k32 = (unsigned)(bucket[i] >> 32);
                if ((k32 & hm) == prefix) atomicAdd(&hist[(k32 >> shift) & 0xFFu], 1u);
            }
            __syncthreads();
            if (tid == 0){
                int acc = 0, d = 255;
                for (; d > 0; d--){ if (acc + (int)hist[d] >= need) break; acc += (int)hist[d]; }
                sh_prefix = prefix | ((unsigned)d << shift);
                sh_need   = need - acc;
            }
            __syncthreads();
            prefix = sh_prefix; need = sh_need;
            __syncthreads();
        }
        if (tid == 0) sn = 0;
        __syncthreads();
        for (int i = tid; i < n; i += 256){
            unsigned long long kk = bucket[i];
            if ((unsigned)(kk >> 32) >= prefix){
                int p = atomicAdd(&sn, 1);
                if (p < 512) skey[p] = kk;
            }
        }
        __syncthreads();
        int cc = sn < 512 ? sn : 512;
        for (int i = tid; i < 512; i += 256) if (i >= cc) skey[i] = 0ull;
    }
    __syncthreads();

    // bitonic sort 512, descending (key64 = value desc, then index asc)
    for (int k = 2; k <= 512; k <<= 1){
        for (int j = k>>1; j > 0; j >>= 1){
            for (int idx = tid; idx < 512; idx += 256){
                int ixj = idx ^ j;
                if (ixj > idx){
                    unsigned long long x = skey[idx], y = skey[ixj];
                    bool up = ((idx & k) == 0);
                    if ((up && x < y) || (!up && x > y)){ skey[idx] = y; skey[ixj] = x; }
                }
            }
            __syncthreads();
        }
    }

    int Ksel = n < KPRE ? n : KPRE;

    // decode boxes for top candidates (unfused f32, double exp -> f32)
    __shared__ float4 sbox[256];
    __shared__ float  sarea[256];
    if (tid < Ksel){
        unsigned long long kk = skey[tid];
        unsigned a = 0xFFFFFFFFu - (unsigned)(kk & 0xFFFFFFFFull);
        float4 anc = anchors[a];
        float4 t   = ybbox[(size_t)b*NA + a];
        float ha = anc.z - anc.x, wa = anc.w - anc.y;
        float cya = __fadd_rn(anc.x, __fmul_rn(0.5f, ha));
        float cxa = __fadd_rn(anc.y, __fmul_rn(0.5f, wa));
        float cy  = __fadd_rn(cya, __fmul_rn(t.x, ha));
        float cx  = __fadd_rn(cxa, __fmul_rn(t.y, wa));
        float h   = __fmul_rn(ha, (float)exp((double)t.z));
        float w   = __fmul_rn(wa, (float)exp((double)t.w));
        float4 bx;
        bx.x = __fadd_rn(cy, -__fmul_rn(0.5f, h));
        bx.y = __fadd_rn(cx, -__fmul_rn(0.5f, w));
        bx.z = __fadd_rn(cy,  __fmul_rn(0.5f, h));
        bx.w = __fadd_rn(cx,  __fmul_rn(0.5f, w));
        sbox[tid]  = bx;
        sarea[tid] = __fmul_rn(bx.z - bx.x, bx.w - bx.y);
    }
    __syncthreads();

    // IoU bitmask matrix
    __shared__ unsigned smask[256][8];
    if (tid < Ksel){
        float4 bi = sbox[tid]; float ai = sarea[tid];
        for (int w = 0; w < 8; w++){
            unsigned mm = 0;
            int jb = w*32, je = min(jb + 32, Ksel);
            for (int j = jb; j < je; j++){
                float4 bj = sbox[j];
                float ih = fmaxf(fminf(bi.z, bj.z) - fmaxf(bi.x, bj.x), 0.f);
                float iw = fmaxf(fminf(bi.w, bj.w) - fmaxf(bi.y, bj.y), 0.f);
                float inter = __fmul_rn(ih, iw);
                float den = __fadd_rn(__fadd_rn(__fadd_rn(ai, sarea[j]), -inter), 1e-8f);
                if (__fdiv_rn(inter, den) > 0.5f) mm |= 1u << (j - jb);
            }
            smask[tid][w] = mm;
        }
    }
    __syncthreads();

    // warp bit-sweep greedy NMS (lanes 0..7 hold 32-bit suppression chunks)
    __shared__ unsigned skeep[8];
    if (tid < 8){
        unsigned sup = 0, keep = 0;
        for (int i = 0; i < Ksel; i++){
            int w = i >> 5;
            unsigned supw = __shfl_sync(0xFFu, sup, w);
            if (!((supw >> (i & 31)) & 1u)){
                if (tid == w) keep |= 1u << (i & 31);
                sup |= smask[i][tid];
            }
        }
        skeep[tid] = keep;
    }
    __syncthreads();

    __shared__ int sbase;
    if (tid == 0){
        int tot = 0;
        #pragma unroll
        for (int w = 0; w < 8; w++) tot += __popc(skeep[w]);
        if (tot > MAXPC) tot = MAXPC;
        sbase = atomicAdd(&g_ccnt[b], tot);
    }
    __syncthreads();

    if (tid < Ksel){
        int w = tid >> 5, bp = tid & 31;
        if ((skeep[w] >> bp) & 1u){
            int r = 0;
            for (int ww = 0; ww < w; ww++) r += __popc(skeep[ww]);
            r += __popc(skeep[w] & ((1u << bp) - 1u));
            if (r < MAXPC){
                float logit = finv((unsigned)(skey[tid] >> 32));
                float score = (float)(1.0 / (1.0 + exp(-(double)logit)));
                unsigned flat = (unsigned)(c*KPRE + tid);
                int slot = sbase + r;
                g_ckey[b*CANDCAP + slot] =
                    ((unsigned long long)fkey(score) << 32) | (0xFFFFFFFFu - flat);
                g_cbox[b*CANDCAP + slot] = sbox[tid];
            }
        }
    }
}

// ---------------- kernel 3: per-batch top-100, rescale, NMS@0.7, output ---
__global__ void __launch_bounds__(256) k_final(const int* __restrict__ ohs,
                                               const int* __restrict__ ows,
                                               float* __restrict__ out){
    int b = blockIdx.x, tid = threadIdx.x;
    int m = g_ccnt[b]; m = m > CANDCAP ? CANDCAP : m;
    const unsigned long long* __restrict__ ck = &g_ckey[b*CANDCAP];

    __shared__ unsigned long long skey[512];
    __shared__ int sslot[512];
    __shared__ unsigned hist[256];
    __shared__ unsigned sh_prefix;
    __shared__ int sh_need, sn;

    int Msel = m < MAXTOT ? m : MAXTOT;
    if (m <= MAXTOT){
        for (int i = tid; i < 512; i += 256){
            if (i < m){ skey[i] = ck[i]; sslot[i] = i; }
            else      { skey[i] = 0ull; sslot[i] = 0; }
        }
    } else {
        unsigned prefix = 0; int need = MAXTOT;
        for (int shift = 24; shift >= 0; shift -= 8){
            hist[tid] = 0;
            __syncthreads();
            unsigned hm = (shift == 24) ? 0u : (0xFFFFFFFFu << (shift+8));
            for (int i = tid; i < m; i += 256){
                unsigned k32 = (unsigned)(ck[i] >> 32);
                if ((k32 & hm) == prefix) atomicAdd(&hist[(k32 >> shift) & 0xFFu], 1u);
            }
            __syncthreads();
            if (tid == 0){
                int acc = 0, d = 255;
                for (; d > 0; d--){ if (acc + (int)hist[d] >= need) break; acc += (int)hist[d]; }
                sh_prefix = prefix | ((unsigned)d << shift);
                sh_need   = need - acc;
            }
            __syncthreads();
            prefix = sh_prefix; need = sh_need;
            __syncthreads();
        }
        if (tid == 0) sn = 0;
        __syncthreads();
        for (int i = tid; i < m; i += 256){
            unsigned long long kk = ck[i];
            if ((unsigned)(kk >> 32) >= prefix){
                int p = atomicAdd(&sn, 1);
                if (p < 512){ skey[p] = kk; sslot[p] = i; }
            }
        }
        __syncthreads();
        int cc = sn < 512 ? sn : 512;
        for (int i = tid; i < 512; i += 256) if (i >= cc){ skey[i] = 0ull; sslot[i] = 0; }
    }
    __syncthreads();

    // bitonic sort 512 desc, with slot payload
    for (int k = 2; k <= 512; k <<= 1){
        for (int j = k>>1; j > 0; j >>= 1){
            for (int idx = tid; idx < 512; idx += 256){
                int ixj = idx ^ j;
                if (ixj > idx){
                    unsigned long long x = skey[idx], y = skey[ixj];
                    bool up = ((idx & k) == 0);
                    if ((up && x < y) || (!up && x > y)){
                        skey[idx] = y; skey[ixj] = x;
                        int s = sslot[idx]; sslot[idx] = sslot[ixj]; sslot[ixj] = s;
                    }
                }
            }
            __syncthreads();
        }
    }

    // rescale + clip
    __shared__ float4 rbox[128];
    __shared__ float  rarea[128];
    float fh = (float)ohs[b], fw = (float)ows[b];
    float rh = __fdiv_rn(fh, 512.f), rw = __fdiv_rn(fw, 512.f);
    if (tid < Msel){
        float4 bx = g_cbox[b*CANDCAP + sslot[tid]];
        float y1 = fminf(fmaxf(__fmul_rn(bx.x, rh), 0.f), fh);
        float x1 = fminf(fmaxf(__fmul_rn(bx.y, rw), 0.f), fw);
        float y2 = fminf(fmaxf(__fmul_rn(bx.z, rh), 0.f), fh);
        float x2 = fminf(fmaxf(__fmul_rn(bx.w, rw), 0.f), fw);
        rbox[tid]  = make_float4(y1, x1, y2, x2);
        rarea[tid] = __fmul_rn(y2 - y1, x2 - x1);
    }
    __syncthreads();

    __shared__ unsigned smask2[128][4];
    if (tid < Msel){
        float4 bi = rbox[tid]; float ai = rarea[tid];
        for (int w = 0; w < 4; w++){
            unsigned mm = 0;
            int jb = w*32, je = min(jb + 32, Msel);
            for (int j = jb; j < je; j++){
                float4 bj = rbox[j];
                float ih = fmaxf(fminf(bi.z, bj.z) - fmaxf(bi.x, bj.x), 0.f);
                float iw = fmaxf(fminf(bi.w, bj.w) - fmaxf(bi.y, bj.y), 0.f);
                float inter = __fmul_rn(ih, iw);
                float den = __fadd_rn(__fadd_rn(__fadd_rn(ai, rarea[j]), -inter), 1e-8f);
                if (__fdiv_rn(inter, den) > 0.7f) mm |= 1u << (j - jb);
            }
            smask2[tid][w] = mm;
        }
    }
    __syncthreads();

    __shared__ unsigned skeep2[4];
    if (tid < 4){
        unsigned sup = 0, keep = 0;
        for (int i = 0; i < Msel; i++){
            int w = i >> 5;
            unsigned supw = __shfl_sync(0xFu, sup, w);
            if (!((supw >> (i & 31)) & 1u)){
                if (tid == w) keep |= 1u << (i & 31);
                sup |= smask2[i][tid];
            }
        }
        skeep2[tid] = keep;
    }
    __syncthreads();

    // zero all output slots for this batch (output is poisoned)
    for (int i = tid; i < MAXTOT; i += 256){
        int o = b*MAXTOT + i;
        out[(size_t)o*4+0] = 0.f; out[(size_t)o*4+1] = 0.f;
        out[(size_t)o*4+2] = 0.f; out[(size_t)o*4+3] = 0.f;
        out[NB*MAXTOT*4 + o] = 0.f;
        out[NB*MAXTOT*5 + o] = 0.f;
    }
    __syncthreads();

    int nv = __popc(skeep2[0]) + __popc(skeep2[1]) + __popc(skeep2[2]) + __popc(skeep2[3]);
    if (tid == 0) out[NB*MAXTOT*6 + b] = (float)nv;

    if (tid < Msel){
        int w = tid >> 5, bp = tid & 31;
        if ((skeep2[w] >> bp) & 1u){
            int r = 0;
            for (int ww = 0; ww < w; ww++) r += __popc(skeep2[ww]);
            r += __popc(skeep2[w] & ((1u << bp) - 1u));
            float score = finv((unsigned)(skey[tid] >> 32));
            unsigned flat = 0xFFFFFFFFu - (unsigned)(skey[tid] & 0xFFFFFFFFull);
            float cls = (float)(flat >> 8);   // flat / KPRE
            int o = b*MAXTOT + r;
            float4 rb = rbox[tid];
            out[(size_t)o*4+0] = rb.x; out[(size_t)o*4+1] = rb.y;
            out[(size_t)o*4+2] = rb.z; out[(size_t)o*4+3] = rb.w;
            out[NB*MAXTOT*4 + o] = score;
            out[NB*MAXTOT*5 + o] = cls;
        }
    }
}

// ---------------- launch ---------------------------------------------------
extern "C" void kernel_launch(void* const* d_in, const int* in_sizes, int n_in,
                              void* d_out, int out_size){
    const float* ycls    = (const float*)d_in[0];
    const float* ybbox   = (const float*)d_in[1];
    const float* anchors = (const float*)d_in[2];
    const int*   ohs     = (const int*)d_in[3];
    const int*   ows     = (const int*)d_in[4];

    k_zero  <<<3, 256>>>();
    k_filter<<<2048, 256>>>((const float4*)ycls);
    k_class <<<NBC, 256>>>((const float4*)ybbox, (const float4*)anchors);
    k_final <<<NB, 256>>>(ohs, ows, (float*)d_out);
}

// round 2
// speedup vs baseline: 3.3761x; 3.3761x over previous
#include <cuda_runtime.h>
#include <math.h>

#define NB 8
#define NA 49104
#define NC 80
#define NBC (NB*NC)
#define KPRE 256
#define CAP 12288
#define MAXPC 100
#define MAXTOT 100
#define CANDCAP (NC*MAXPC)
#define THRL -2.9444389791664403f
#define CNTSH 6            // counter stride = 64 ints = 256B (kills L2 atomic serialization)

// ---------------- scratch (static device globals; no runtime allocation) ----
static __device__ int g_cnt[NBC << CNTSH];
static __device__ unsigned long long g_bucket[(size_t)NBC*CAP];
static __device__ int g_ccnt[NB];
static __device__ unsigned long long g_ckey[NB*CANDCAP];
static __device__ float4 g_cbox[NB*CANDCAP];

__device__ __forceinline__ unsigned fkey(float f){
    unsigned u = __float_as_uint(f);
    return (u & 0x80000000u) ? ~u : (u | 0x80000000u);
}
__device__ __forceinline__ float finv(unsigned o){
    unsigned u = (o & 0x80000000u) ? (o & 0x7FFFFFFFu) : ~o;
    return __uint_as_float(u);
}

// ---------------- parallel radix cutoff: rank-K threshold over key32 -------
// 3 passes (11/11/10 bits), warp-aggregated histogram, parallel suffix scan.
// hist: shared[2048]. Returns prefix so that {k32 >= prefix} has >= K items
// and is the minimal such digit-refined set. Call with all 256 threads.
__device__ unsigned radix_cutoff(const unsigned long long* __restrict__ data,
                                 int n, int K, unsigned* hist,
                                 unsigned* sh_pref, int* sh_need, int tid){
    unsigned prefix = 0; int need = K; unsigned hm = 0;
    #pragma unroll
    for (int p = 0; p < 3; p++){
        const int shift   = (p == 0) ? 21 : (p == 1) ? 10 : 0;
        const unsigned dm = (p == 2) ? 0x3FFu : 0x7FFu;
        for (int k = tid; k < 2048; k += 256) hist[k] = 0;
        __syncthreads();
        int iters = (n + 255) >> 8;
        for (int it = 0; it < iters; it++){
            int i = it*256 + tid;
            unsigned k32 = 0; bool act = false;
            if (i < n){
                k32 = (unsigned)(data[i] >> 32);
                act = ((k32 & hm) == prefix);
            }
            unsigned bm = __ballot_sync(0xFFFFFFFFu, act);
            if (act){
                unsigned d = (k32 >> shift) & dm;
                unsigned peers = __match_any_sync(bm, d);
                if ((unsigned)(__ffs(peers) - 1) == (tid & 31u))
                    atomicAdd(&hist[d], __popc(peers));
            }
        }
        __syncthreads();
        // inclusive suffix scan over 2048 (Hillis-Steele)
        for (int off = 1; off < 2048; off <<= 1){
            unsigned tmp[8];
            #pragma unroll
            for (int k = 0; k < 8; k++){
                int idx = tid + k*256;
                unsigned v = hist[idx];
                if (idx + off < 2048) v += hist[idx + off];
                tmp[k] = v;
            }
            __syncthreads();
            #pragma unroll
            for (int k = 0; k < 8; k++) hist[tid + k*256] = tmp[k];
            __syncthreads();
        }
        // largest d with S[d] >= need
        #pragma unroll
        for (int k = 0; k < 8; k++){
            int d = tid + k*256;
            int Sd  = (int)hist[d];
            int Sd1 = (d + 1 < 2048) ? (int)hist[d+1] : 0;
            if (Sd >= need && Sd1 < need){
                *sh_pref = prefix | ((unsigned)d << shift);
                *sh_need = need - Sd1;
            }
        }
        __syncthreads();
        prefix = *sh_pref; need = *sh_need;
        hm |= (dm << shift);
        __syncthreads();
    }
    return prefix;
}

// ---------------- kernel 0: zero counters --------------------------------
__global__ void k_zero(){
    int t = blockIdx.x*blockDim.x + threadIdx.x;
    if (t < (NBC << CNTSH)) g_cnt[t] = 0;
    if (t < NB)  g_ccnt[t] = 0;
}

// ---------------- kernel 1: threshold filter + bucket scatter -------------
__global__ void __launch_bounds__(256) k_filter(const float4* __restrict__ ycls){
    const long long tot4 = (long long)NB*NA*NC/4;
    long long stride = (long long)gridDim.x*blockDim.x;
    for (long long g = blockIdx.x*(long long)blockDim.x + threadIdx.x; g < tot4; g += stride){
        float4 v = ycls[g];
        if (v.x > THRL || v.y > THRL || v.z > THRL || v.w > THRL){
            long long i0 = g*4;
            long long t  = i0 / NC;
            int c0 = (int)(i0 - t*NC);       // multiple of 4 -> same anchor for all 4
            int a  = (int)(t % NA);
            int b  = (int)(t / NA);
            unsigned inva = 0xFFFFFFFFu - (unsigned)a;
            float vv[4] = {v.x, v.y, v.z, v.w};
            #pragma unroll
            for (int k = 0; k < 4; k++){
                if (vv[k] > THRL){
                    int bc = b*NC + c0 + k;
                    int pos = atomicAdd(&g_cnt[bc << CNTSH], 1);
                    if (pos < CAP)
                        g_bucket[(size_t)bc*CAP + pos] =
                            ((unsigned long long)fkey(vv[k]) << 32) | inva;
                }
            }
        }
    }
}

// ---------------- kernel 2: per-(b,c) top-256 + NMS@0.5 -------------------
__global__ void __launch_bounds__(256) k_class(const float4* __restrict__ ybbox,
                                               const float4* __restrict__ anchors){
    int bc = blockIdx.x, b = bc/NC, c = bc - b*NC, tid = threadIdx.x;
    int n = g_cnt[bc << CNTSH]; n = n > CAP ? CAP : n;
    if (n == 0) return;
    const unsigned long long* __restrict__ bucket = &g_bucket[(size_t)bc*CAP];

    __shared__ unsigned hist[2048];
    __shared__ unsigned sh_prefix;
    __shared__ int sh_need, sn;
    __shared__ unsigned long long skey[512];

    if (n <= KPRE){
        for (int i = tid; i < 512; i += 256) skey[i] = (i < n) ? bucket[i] : 0ull;
        __syncthreads();
    } else {
        unsigned prefix = radix_cutoff(bucket, n, KPRE, hist, &sh_prefix, &sh_need, tid);
        if (tid == 0) sn = 0;
        __syncthreads();
        for (int i = tid; i < n; i += 256){
            unsigned long long kk = bucket[i];
            if ((unsigned)(kk >> 32) >= prefix){
                int p = atomicAdd(&sn, 1);
                if (p < 512) skey[p] = kk;
            }
        }
        __syncthreads();
        int cc = sn < 512 ? sn : 512;
        for (int i = tid; i < 512; i += 256) if (i >= cc) skey[i] = 0ull;
        __syncthreads();
    }

    // bitonic sort 512 desc (value desc, then anchor index asc via ~idx)
    for (int k = 2; k <= 512; k <<= 1){
        for (int j = k>>1; j > 0; j >>= 1){
            for (int idx = tid; idx < 512; idx += 256){
                int ixj = idx ^ j;
                if (ixj > idx){
                    unsigned long long x = skey[idx], y = skey[ixj];
                    bool up = ((idx & k) == 0);
                    if ((up && x < y) || (!up && x > y)){ skey[idx] = y; skey[ixj] = x; }
                }
            }
            __syncthreads();
        }
    }

    int Ksel = n < KPRE ? n : KPRE;

    // decode boxes (unfused f32)
    __shared__ float4 sbox[256];
    __shared__ float  sarea[256];
    if (tid < Ksel){
        unsigned long long kk = skey[tid];
        unsigned a = 0xFFFFFFFFu - (unsigned)(kk & 0xFFFFFFFFull);
        float4 anc = anchors[a];
        float4 t   = ybbox[(size_t)b*NA + a];
        float ha = anc.z - anc.x, wa = anc.w - anc.y;
        float cya = __fadd_rn(anc.x, __fmul_rn(0.5f, ha));
        float cxa = __fadd_rn(anc.y, __fmul_rn(0.5f, wa));
        float cy  = __fadd_rn(cya, __fmul_rn(t.x, ha));
        float cx  = __fadd_rn(cxa, __fmul_rn(t.y, wa));
        float h   = __fmul_rn(ha, expf(t.z));
        float w   = __fmul_rn(wa, expf(t.w));
        float4 bx;
        bx.x = __fadd_rn(cy, -__fmul_rn(0.5f, h));
        bx.y = __fadd_rn(cx, -__fmul_rn(0.5f, w));
        bx.z = __fadd_rn(cy,  __fmul_rn(0.5f, h));
        bx.w = __fadd_rn(cx,  __fmul_rn(0.5f, w));
        sbox[tid]  = bx;
        sarea[tid] = __fmul_rn(bx.z - bx.x, bx.w - bx.y);
    }
    __syncthreads();

    // IoU bitmask matrix
    __shared__ unsigned smask[256][8];
    if (tid < Ksel){
        float4 bi = sbox[tid]; float ai = sarea[tid];
        for (int w = 0; w < 8; w++){
            unsigned mm = 0;
            int jb = w*32, je = min(jb + 32, Ksel);
            for (int j = jb; j < je; j++){
                float4 bj = sbox[j];
                float ih = fmaxf(fminf(bi.z, bj.z) - fmaxf(bi.x, bj.x), 0.f);
                float iw = fmaxf(fminf(bi.w, bj.w) - fmaxf(bi.y, bj.y), 0.f);
                float inter = __fmul_rn(ih, iw);
                float den = __fadd_rn(__fadd_rn(__fadd_rn(ai, sarea[j]), -inter), 1e-8f);
                if (__fdiv_rn(inter, den) > 0.5f) mm |= 1u << (j - jb);
            }
            smask[tid][w] = mm;
        }
    }
    __syncthreads();

    // warp bit-sweep greedy NMS
    __shared__ unsigned skeep[8];
    if (tid < 8){
        unsigned sup = 0, keep = 0;
        for (int i = 0; i < Ksel; i++){
            int w = i >> 5;
            unsigned supw = __shfl_sync(0xFFu, sup, w);
            if (!((supw >> (i & 31)) & 1u)){
                if (tid == w) keep |= 1u << (i & 31);
                sup |= smask[i][tid];
            }
        }
        skeep[tid] = keep;
    }
    __syncthreads();

    __shared__ int sbase;
    if (tid == 0){
        int tot = 0;
        #pragma unroll
        for (int w = 0; w < 8; w++) tot += __popc(skeep[w]);
        if (tot > MAXPC) tot = MAXPC;
        sbase = atomicAdd(&g_ccnt[b], tot);
    }
    __syncthreads();

    if (tid < Ksel){
        int w = tid >> 5, bp = tid & 31;
        if ((skeep[w] >> bp) & 1u){
            int r = 0;
            for (int ww = 0; ww < w; ww++) r += __popc(skeep[ww]);
            r += __popc(skeep[w] & ((1u << bp) - 1u));
            if (r < MAXPC){
                float logit = finv((unsigned)(skey[tid] >> 32));
                float score = 1.0f / (1.0f + expf(-logit));
                unsigned flat = (unsigned)(c*KPRE + tid);
                int slot = sbase + r;
                g_ckey[b*CANDCAP + slot] =
                    ((unsigned long long)fkey(score) << 32) | (0xFFFFFFFFu - flat);
                g_cbox[b*CANDCAP + slot] = sbox[tid];
            }
        }
    }
}

// ---------------- kernel 3: per-batch top-100, rescale, NMS@0.7, output ---
__global__ void __launch_bounds__(256) k_final(const int* __restrict__ ohs,
                                               const int* __restrict__ ows,
                                               float* __restrict__ out){
    int b = blockIdx.x, tid = threadIdx.x;
    int m = g_ccnt[b]; m = m > CANDCAP ? CANDCAP : m;
    const unsigned long long* __restrict__ ck = &g_ckey[b*CANDCAP];

    __shared__ unsigned long long skey[512];
    __shared__ int sslot[512];
    __shared__ unsigned hist[2048];
    __shared__ unsigned sh_prefix;
    __shared__ int sh_need, sn;

    int Msel = m < MAXTOT ? m : MAXTOT;
    if (m <= MAXTOT){
        for (int i = tid; i < 512; i += 256){
            if (i < m){ skey[i] = ck[i]; sslot[i] = i; }
            else      { skey[i] = 0ull; sslot[i] = 0; }
        }
        __syncthreads();
    } else {
        unsigned prefix = radix_cutoff(ck, m, MAXTOT, hist, &sh_prefix, &sh_need, tid);
        if (tid == 0) sn = 0;
        __syncthreads();
        for (int i = tid; i < m; i += 256){
            unsigned long long kk = ck[i];
            if ((unsigned)(kk >> 32) >= prefix){
                int p = atomicAdd(&sn, 1);
                if (p < 512){ skey[p] = kk; sslot[p] = i; }
            }
        }
        __syncthreads();
        int cc = sn < 512 ? sn : 512;
        for (int i = tid; i < 512; i += 256) if (i >= cc){ skey[i] = 0ull; sslot[i] = 0; }
        __syncthreads();
    }

    // bitonic sort 512 desc with slot payload
    for (int k = 2; k <= 512; k <<= 1){
        for (int j = k>>1; j > 0; j >>= 1){
            for (int idx = tid; idx < 512; idx += 256){
                int ixj = idx ^ j;
                if (ixj > idx){
                    unsigned long long x = skey[idx], y = skey[ixj];
                    bool up = ((idx & k) == 0);
                    if ((up && x < y) || (!up && x > y)){
                        skey[idx] = y; skey[ixj] = x;
                        int s = sslot[idx]; sslot[idx] = sslot[ixj]; sslot[ixj] = s;
                    }
                }
            }
            __syncthreads();
        }
    }

    // rescale + clip
    __shared__ float4 rbox[128];
    __shared__ float  rarea[128];
    float fh = (float)ohs[b], fw = (float)ows[b];
    float rh = __fdiv_rn(fh, 512.f), rw = __fdiv_rn(fw, 512.f);
    if (tid < Msel){
        float4 bx = g_cbox[b*CANDCAP + sslot[tid]];
        float y1 = fminf(fmaxf(__fmul_rn(bx.x, rh), 0.f), fh);
        float x1 = fminf(fmaxf(__fmul_rn(bx.y, rw), 0.f), fw);
        float y2 = fminf(fmaxf(__fmul_rn(bx.z, rh), 0.f), fh);
        float x2 = fminf(fmaxf(__fmul_rn(bx.w, rw), 0.f), fw);
        rbox[tid]  = make_float4(y1, x1, y2, x2);
        rarea[tid] = __fmul_rn(y2 - y1, x2 - x1);
    }
    __syncthreads();

    __shared__ unsigned smask2[128][4];
    if (tid < Msel){
        float4 bi = rbox[tid]; float ai = rarea[tid];
        for (int w = 0; w < 4; w++){
            unsigned mm = 0;
            int jb = w*32, je = min(jb + 32, Msel);
            for (int j = jb; j < je; j++){
                float4 bj = rbox[j];
                float ih = fmaxf(fminf(bi.z, bj.z) - fmaxf(bi.x, bj.x), 0.f);
                float iw = fmaxf(fminf(bi.w, bj.w) - fmaxf(bi.y, bj.y), 0.f);
                float inter = __fmul_rn(ih, iw);
                float den = __fadd_rn(__fadd_rn(__fadd_rn(ai, rarea[j]), -inter), 1e-8f);
                if (__fdiv_rn(inter, den) > 0.7f) mm |= 1u << (j - jb);
            }
            smask2[tid][w] = mm;
        }
    }
    __syncthreads();

    __shared__ unsigned skeep2[4];
    if (tid < 4){
        unsigned sup = 0, keep = 0;
        for (int i = 0; i < Msel; i++){
            int w = i >> 5;
            unsigned supw = __shfl_sync(0xFu, sup, w);
            if (!((supw >> (i & 31)) & 1u)){
                if (tid == w) keep |= 1u << (i & 31);
                sup |= smask2[i][tid];
            }
        }
        skeep2[tid] = keep;
    }
    __syncthreads();

    // zero output slots (output buffer is poisoned)
    for (int i = tid; i < MAXTOT; i += 256){
        int o = b*MAXTOT + i;
        out[(size_t)o*4+0] = 0.f; out[(size_t)o*4+1] = 0.f;
        out[(size_t)o*4+2] = 0.f; out[(size_t)o*4+3] = 0.f;
        out[NB*MAXTOT*4 + o] = 0.f;
        out[NB*MAXTOT*5 + o] = 0.f;
    }
    __syncthreads();

    int nv = __popc(skeep2[0]) + __popc(skeep2[1]) + __popc(skeep2[2]) + __popc(skeep2[3]);
    if (tid == 0) out[NB*MAXTOT*6 + b] = (float)nv;

    if (tid < Msel){
        int w = tid >> 5, bp = tid & 31;
        if ((skeep2[w] >> bp) & 1u){
            int r = 0;
            for (int ww = 0; ww < w; ww++) r += __popc(skeep2[ww]);
            r += __popc(skeep2[w] & ((1u << bp) - 1u));
            float score = finv((unsigned)(skey[tid] >> 32));
            unsigned flat = 0xFFFFFFFFu - (unsigned)(skey[tid] & 0xFFFFFFFFull);
            float cls = (float)(flat >> 8);   // flat / KPRE
            int o = b*MAXTOT + r;
            float4 rb = rbox[tid];
            out[(size_t)o*4+0] = rb.x; out[(size_t)o*4+1] = rb.y;
            out[(size_t)o*4+2] = rb.z; out[(size_t)o*4+3] = rb.w;
            out[NB*MAXTOT*4 + o] = score;
            out[NB*MAXTOT*5 + o] = cls;
        }
    }
}

// ---------------- launch ---------------------------------------------------
extern "C" void kernel_launch(void* const* d_in, const int* in_sizes, int n_in,
                              void* d_out, int out_size){
    const float* ycls    = (const float*)d_in[0];
    const float* ybbox   = (const float*)d_in[1];
    const float* anchors = (const float*)d_in[2];
    const int*   ohs     = (const int*)d_in[3];
    const int*   ows     = (const int*)d_in[4];

    k_zero  <<<161, 256>>>();
    k_filter<<<2048, 256>>>((const float4*)ycls);
    k_class <<<NBC, 256>>>((const float4*)ybbox, (const float4*)anchors);
    k_final <<<NB, 256>>>(ohs, ows, (float*)d_out);
}